// round 4
// baseline (speedup 1.0000x reference)
#include <cuda_runtime.h>
#include <cstdint>

#define TT     48000
#define NCH    512
#define NW     10                 // warps per block
#define NTHR   (NW * 32)          // 320
#define LCH    15                 // samples per lane per tile (odd -> conflict-free LDS)
#define WSLICE (32 * LCH)         // 480 samples per warp per tile
#define TILE   (NW * WSLICE)      // 4800 samples per tile
#define NTILE  (TT / TILE)        // 10

#define FULLM 0xffffffffu

// 2x2 matrix multiply: O = A * B
#define MM(o00,o01,o10,o11, a00,a01,a10,a11, b00,b01,b10,b11) do { \
    float t00 = a00*b00 + a01*b10; \
    float t01 = a00*b01 + a01*b11; \
    float t10 = a10*b00 + a11*b10; \
    float t11 = a10*b01 + a11*b11; \
    o00=t00; o01=t01; o10=t10; o11=t11; } while(0)

__device__ __forceinline__ uint32_t s2u(const void* p) {
    return (uint32_t)__cvta_generic_to_shared(p);
}
__device__ __forceinline__ void cp_async16(uint32_t saddr, const void* gaddr) {
    asm volatile("cp.async.cg.shared.global [%0], [%1], 16;"
                 :: "r"(saddr), "l"(gaddr) : "memory");
}
__device__ __forceinline__ void cp_commit() {
    asm volatile("cp.async.commit_group;" ::: "memory");
}
template<int N> __device__ __forceinline__ void cp_wait() {
    asm volatile("cp.async.wait_group %0;" :: "n"(N) : "memory");
}
__device__ __forceinline__ void st_release_s32(uint32_t addr, int v) {
    asm volatile("st.release.cta.shared.b32 [%0], %1;" :: "r"(addr), "r"(v) : "memory");
}
__device__ __forceinline__ int ld_acquire_s32(uint32_t addr) {
    int v;
    asm volatile("ld.acquire.cta.shared.b32 %0, [%1];" : "=r"(v) : "r"(addr) : "memory");
    return v;
}

__global__ __launch_bounds__(NTHR, 4) void biquad_kernel(
    const float* __restrict__ x,
    const float* __restrict__ b0v, const float* __restrict__ b1v,
    const float* __restrict__ b2v, const float* __restrict__ a1v,
    const float* __restrict__ a2v, float* __restrict__ y)
{
    __shared__ __align__(16) float xs[NW * 2 * WSLICE];  // per-warp double buffers
    __shared__ float sP[6 * 4];          // P[0..4] = Q^(2^k), then W = Q^32
    __shared__ float sCar[NW * 2];       // carry mailboxes (z1,z2)
    __shared__ int   sTag[NW];           // release/acquire tags

    const int ch   = blockIdx.x;
    const int tid  = threadIdx.x;
    const int lane = tid & 31;
    const int w    = tid >> 5;

    const float B0 = b0v[ch], B1 = b1v[ch], B2 = b2v[ch];
    const float A1 = a1v[ch], A2 = a2v[ch];
    const float nA1 = -A1, nA2 = -A2;

    // Per-sample transition s' = M s + c(x), M = [[-A1,1],[-A2,0]].
    // Q = M^LCH via square-and-multiply; P[k] = Q^(2^k); W = Q^32.
    float p00[5], p01[5], p10[5], p11[5];
    {
        float m00 = nA1, m01 = 1.f, m10 = nA2, m11 = 0.f;
        float r00 = 1.f, r01 = 0.f, r10 = 0.f, r11 = 1.f;
        int e = LCH;
        while (e) {
            if (e & 1) { MM(r00,r01,r10,r11, r00,r01,r10,r11, m00,m01,m10,m11); }
            e >>= 1;
            if (e) { MM(m00,m01,m10,m11, m00,m01,m10,m11, m00,m01,m10,m11); }
        }
        p00[0] = r00; p01[0] = r01; p10[0] = r10; p11[0] = r11;
        #pragma unroll
        for (int k = 1; k < 5; ++k) {
            MM(p00[k],p01[k],p10[k],p11[k],
               p00[k-1],p01[k-1],p10[k-1],p11[k-1],
               p00[k-1],p01[k-1],p10[k-1],p11[k-1]);
        }
    }

    // Qlane = Q^lane (powers of one matrix commute)
    float q00 = 1.f, q01 = 0.f, q10 = 0.f, q11 = 1.f;
    #pragma unroll
    for (int k = 0; k < 5; ++k) {
        if ((lane >> k) & 1) {
            MM(q00,q01,q10,q11, p00[k],p01[k],p10[k],p11[k], q00,q01,q10,q11);
        }
    }

    if (tid == 0) {
        #pragma unroll
        for (int k = 0; k < 5; ++k) {
            sP[k*4+0] = p00[k]; sP[k*4+1] = p01[k];
            sP[k*4+2] = p10[k]; sP[k*4+3] = p11[k];
        }
        float W00, W01, W10, W11;  // Q^32
        MM(W00,W01,W10,W11, p00[4],p01[4],p10[4],p11[4], p00[4],p01[4],p10[4],p11[4]);
        sP[20] = W00; sP[21] = W01; sP[22] = W10; sP[23] = W11;
    }
    if (tid < NW) sTag[tid] = 0;
    __syncthreads();   // the only block-wide barrier

    const float* __restrict__ xg = x + (size_t)ch * TT;
    float* __restrict__       yg = y + (size_t)ch * TT;
    float* const buf0 = xs + w * (2 * WSLICE);

    // Prefetch tile 0 (this warp's slice)
    {
        const float* src = xg + w * WSLICE;
        uint32_t dst = s2u(buf0);
        #pragma unroll
        for (int i = lane; i < WSLICE / 4; i += 32)
            cp_async16(dst + i * 16, src + i * 4);
        cp_commit();
    }

    for (int t = 0; t < NTILE; ++t) {
        float* const buf = buf0 + (t & 1) * WSLICE;

        if (t + 1 < NTILE) {
            const float* src = xg + (t + 1) * TILE + w * WSLICE;
            uint32_t dst = s2u(buf0 + ((t + 1) & 1) * WSLICE);
            #pragma unroll
            for (int i = lane; i < WSLICE / 4; i += 32)
                cp_async16(dst + i * 16, src + i * 4);
            cp_commit();
            cp_wait<1>();
        } else {
            cp_wait<0>();
        }
        __syncwarp();

        const float* const xc = buf + lane * LCH;

        // ---- pass 1: chunk from zero state (reads x only) ----
        float z1 = 0.f, z2 = 0.f;
        #pragma unroll
        for (int k = 0; k < LCH; ++k) {
            float v  = xc[k];
            float yn = fmaf(B0, v, z1);
            z1 = fmaf(B1, v, fmaf(nA1, yn, z2));
            z2 = fmaf(B2, v, nA2 * yn);
        }

        // ---- warp inclusive affine scan of chunk end-states ----
        float E1 = z1, E2 = z2;
        #pragma unroll
        for (int k = 0; k < 5; ++k) {
            const int d = 1 << k;
            float u1 = __shfl_up_sync(FULLM, E1, d);
            float u2 = __shfl_up_sync(FULLM, E2, d);
            float a = sP[k*4+0], b = sP[k*4+1], c = sP[k*4+2], dd = sP[k*4+3];
            if (lane >= d) {
                E1 = fmaf(a, u1, fmaf(b, u2, E1));
                E2 = fmaf(c, u1, fmaf(dd, u2, E2));
            }
        }
        float e31_1 = __shfl_sync(FULLM, E1, 31);
        float e31_2 = __shfl_sync(FULLM, E2, 31);

        // ---- cross-warp carry handoff (lane 0 only) ----
        float c1 = 0.f, c2 = 0.f;
        if (lane == 0) {
            if (!(w == 0 && t == 0)) {
                const int pred = (w == 0) ? (NW - 1) : (w - 1);
                const int need = (w == 0) ? t : (t + 1);
                uint32_t ta = s2u(&sTag[pred]);
                while (ld_acquire_s32(ta) < need) { __nanosleep(20); }
                c1 = sCar[pred * 2 + 0];
                c2 = sCar[pred * 2 + 1];
            }
            float W00 = sP[20], W01 = sP[21], W10 = sP[22], W11 = sP[23];
            sCar[w * 2 + 0] = fmaf(W00, c1, fmaf(W01, c2, e31_1));
            sCar[w * 2 + 1] = fmaf(W10, c1, fmaf(W11, c2, e31_2));
            st_release_s32(s2u(&sTag[w]), t + 1);
        }
        c1 = __shfl_sync(FULLM, c1, 0);
        c2 = __shfl_sync(FULLM, c2, 0);

        // ---- true start state for this lane's chunk ----
        float Ex1 = __shfl_up_sync(FULLM, E1, 1);
        float Ex2 = __shfl_up_sync(FULLM, E2, 1);
        if (lane == 0) { Ex1 = 0.f; Ex2 = 0.f; }
        z1 = q00 * c1 + q01 * c2 + Ex1;
        z2 = q10 * c1 + q11 * c2 + Ex2;

        // ---- pass 2: reference-form recurrence, y written in place ----
        float* const yc = buf + lane * LCH;
        #pragma unroll
        for (int k = 0; k < LCH; ++k) {
            float v  = xc[k];
            float yn = fmaf(B0, v, z1);
            z1 = fmaf(B1, v, fmaf(nA1, yn, z2));
            z2 = fmaf(B2, v, nA2 * yn);
            yc[k] = yn;
        }
        __syncwarp();

        // ---- store this warp's slice, coalesced float4 ----
        float4* const yg4 = (float4*)(yg + t * TILE + w * WSLICE);
        const float4* const b4 = (const float4*)buf;
        #pragma unroll
        for (int i = lane; i < WSLICE / 4; i += 32)
            yg4[i] = b4[i];
        // no sync needed: next cp.async into this buffer is by the same lane
        // over the same float4 slots it just read (per-lane program order).
    }
}

extern "C" void kernel_launch(void* const* d_in, const int* in_sizes, int n_in,
                              void* d_out, int out_size)
{
    const float* x  = (const float*)d_in[0];
    const float* b0 = (const float*)d_in[1];
    const float* b1 = (const float*)d_in[2];
    const float* b2 = (const float*)d_in[3];
    const float* a1 = (const float*)d_in[4];
    const float* a2 = (const float*)d_in[5];
    float* yo = (float*)d_out;

    biquad_kernel<<<NCH, NTHR>>>(x, b0, b1, b2, a1, a2, yo);
}

// round 5
// speedup vs baseline: 1.6004x; 1.6004x over previous
#include <cuda_runtime.h>
#include <cstdint>

#define TT     48000
#define NCH    512
#define NW     10                 // warps per block
#define NTHR   (NW * 32)          // 320
#define LCH    15                 // samples per lane per tile
#define WSLICE (32 * LCH)         // 480 samples per warp per tile
#define TILE   (NW * WSLICE)      // 4800 samples per tile
#define NTILE  (TT / TILE)        // 10

#define FULLM 0xffffffffu

// 2x2 matrix multiply: O = A * B
#define MM(o00,o01,o10,o11, a00,a01,a10,a11, b00,b01,b10,b11) do { \
    float t00 = a00*b00 + a01*b10; \
    float t01 = a00*b01 + a01*b11; \
    float t10 = a10*b00 + a11*b10; \
    float t11 = a10*b01 + a11*b11; \
    o00=t00; o01=t01; o10=t10; o11=t11; } while(0)

__device__ __forceinline__ uint32_t s2u(const void* p) {
    return (uint32_t)__cvta_generic_to_shared(p);
}
__device__ __forceinline__ void cp_async16(uint32_t saddr, const void* gaddr) {
    asm volatile("cp.async.cg.shared.global [%0], [%1], 16;"
                 :: "r"(saddr), "l"(gaddr) : "memory");
}
__device__ __forceinline__ void cp_commit() {
    asm volatile("cp.async.commit_group;" ::: "memory");
}
template<int N> __device__ __forceinline__ void cp_wait() {
    asm volatile("cp.async.wait_group %0;" :: "n"(N) : "memory");
}

__global__ __launch_bounds__(NTHR, 4) void biquad_kernel(
    const float* __restrict__ x,
    const float* __restrict__ b0v, const float* __restrict__ b1v,
    const float* __restrict__ b2v, const float* __restrict__ a1v,
    const float* __restrict__ a2v, float* __restrict__ y)
{
    __shared__ __align__(16) float xs[NW * 2 * WSLICE];  // per-warp double buffers
    __shared__ float sP[5 * 4];             // P[k] = Q^(2^k)
    __shared__ float sT1[2][NW], sT2[2][NW]; // per-warp tile totals, parity-buffered

    const int ch   = blockIdx.x;
    const int tid  = threadIdx.x;
    const int lane = tid & 31;
    const int w    = tid >> 5;

    const float B0 = b0v[ch], B1 = b1v[ch], B2 = b2v[ch];
    const float A1 = a1v[ch], A2 = a2v[ch];
    const float nA1 = -A1, nA2 = -A2;

    // y-state transition: s[n] = (y[n], y[n-1]),  s' = My s + (f,0),
    // My = [[-A1,-A2],[1,0]].  Q = My^LCH; P[k] = Q^(2^k); W = Q^32 = My^WSLICE.
    float p00[5], p01[5], p10[5], p11[5];
    {
        float m00 = nA1, m01 = nA2, m10 = 1.f, m11 = 0.f;
        float r00 = 1.f, r01 = 0.f, r10 = 0.f, r11 = 1.f;
        int e = LCH;
        while (e) {
            if (e & 1) { MM(r00,r01,r10,r11, r00,r01,r10,r11, m00,m01,m10,m11); }
            e >>= 1;
            if (e) { MM(m00,m01,m10,m11, m00,m01,m10,m11, m00,m01,m10,m11); }
        }
        p00[0] = r00; p01[0] = r01; p10[0] = r10; p11[0] = r11;
        #pragma unroll
        for (int k = 1; k < 5; ++k) {
            MM(p00[k],p01[k],p10[k],p11[k],
               p00[k-1],p01[k-1],p10[k-1],p11[k-1],
               p00[k-1],p01[k-1],p10[k-1],p11[k-1]);
        }
    }
    float W00, W01, W10, W11;  // Q^32
    MM(W00,W01,W10,W11, p00[4],p01[4],p10[4],p11[4], p00[4],p01[4],p10[4],p11[4]);

    // Qlane = Q^lane (powers of one matrix commute)
    float q00 = 1.f, q01 = 0.f, q10 = 0.f, q11 = 1.f;
    #pragma unroll
    for (int k = 0; k < 5; ++k) {
        if ((lane >> k) & 1) {
            MM(q00,q01,q10,q11, p00[k],p01[k],p10[k],p11[k], q00,q01,q10,q11);
        }
    }
    if (tid == 0) {
        #pragma unroll
        for (int k = 0; k < 5; ++k) {
            sP[k*4+0] = p00[k]; sP[k*4+1] = p01[k];
            sP[k*4+2] = p10[k]; sP[k*4+3] = p11[k];
        }
    }
    __syncthreads();

    const float* __restrict__ xg = x + (size_t)ch * TT;
    float* __restrict__       yg = y + (size_t)ch * TT;
    float* const buf0 = xs + w * (2 * WSLICE);

    // Prefetch tile 0 (this warp's slice only)
    {
        const float* src = xg + w * WSLICE;
        uint32_t dst = s2u(buf0);
        #pragma unroll
        for (int i = lane; i < WSLICE / 4; i += 32)
            cp_async16(dst + i * 16, src + i * 4);
        cp_commit();
    }

    float carry1 = 0.f, carry2 = 0.f;   // (y[-1], y[-2]) entering the tile; all threads identical

    for (int t = 0; t < NTILE; ++t) {
        float* const buf = buf0 + (t & 1) * WSLICE;

        if (t + 1 < NTILE) {
            const float* src = xg + (t + 1) * TILE + w * WSLICE;
            uint32_t dst = s2u(buf0 + ((t + 1) & 1) * WSLICE);
            #pragma unroll
            for (int i = lane; i < WSLICE / 4; i += 32)
                cp_async16(dst + i * 16, src + i * 4);
            cp_commit();
            cp_wait<1>();
        } else {
            cp_wait<0>();
        }
        __syncwarp();

        float* const xc = buf + lane * LCH;

        // ---- x lookback for this lane's chunk (read before any overwrite) ----
        float xm1_0, xm2_0;
        if (lane == 0) {
            const int g = t * TILE + w * WSLICE;    // global index of chunk start
            xm1_0 = (g >= 1) ? __ldg(xg + g - 1) : 0.f;
            xm2_0 = (g >= 2) ? __ldg(xg + g - 2) : 0.f;
        } else {
            xm1_0 = xc[-1];
            xm2_0 = xc[-2];
        }

        // ---- pass 1: direct form from zero y-state (reads x only) ----
        float y1 = 0.f, y2 = 0.f, xm1 = xm1_0, xm2 = xm2_0;
        #pragma unroll
        for (int k = 0; k < LCH; ++k) {
            float v  = xc[k];
            float f  = fmaf(B0, v, fmaf(B1, xm1, B2 * xm2));
            float yn = fmaf(nA1, y1, fmaf(nA2, y2, f));
            y2 = y1; y1 = yn; xm2 = xm1; xm1 = v;
        }

        // ---- warp inclusive affine scan of chunk end states (y1,y2) ----
        float E1 = y1, E2 = y2;
        #pragma unroll
        for (int k = 0; k < 5; ++k) {
            const int d = 1 << k;
            float u1 = __shfl_up_sync(FULLM, E1, d);
            float u2 = __shfl_up_sync(FULLM, E2, d);
            float a = sP[k*4+0], b = sP[k*4+1], c = sP[k*4+2], dd = sP[k*4+3];
            if (lane >= d) {
                E1 = fmaf(a, u1, fmaf(b, u2, E1));
                E2 = fmaf(c, u1, fmaf(dd, u2, E2));
            }
        }
        if (lane == 31) { sT1[t & 1][w] = E1; sT2[t & 1][w] = E2; }
        __syncthreads();   // only block barrier per tile

        // ---- cross-warp combine, done redundantly by every thread ----
        float c1 = carry1, c2 = carry2;
        float wc1 = 0.f, wc2 = 0.f;      // state entering this warp's slice
        #pragma unroll
        for (int i = 0; i < NW; ++i) {
            if (i == w) { wc1 = c1; wc2 = c2; }
            float e1 = sT1[t & 1][i], e2 = sT2[t & 1][i];
            float n1 = fmaf(W00, c1, fmaf(W01, c2, e1));
            float n2 = fmaf(W10, c1, fmaf(W11, c2, e2));
            c1 = n1; c2 = n2;
        }
        carry1 = c1; carry2 = c2;        // tile-out state (identical in all threads)

        // ---- true start state of this lane's chunk ----
        float Ex1 = __shfl_up_sync(FULLM, E1, 1);
        float Ex2 = __shfl_up_sync(FULLM, E2, 1);
        if (lane == 0) { Ex1 = 0.f; Ex2 = 0.f; }
        float S1 = q00 * wc1 + q01 * wc2 + Ex1;   // y[start-1]
        float S2 = q10 * wc1 + q11 * wc2 + Ex2;   // y[start-2]

        // ---- pass 2: direct form from true state; overwrite x with y ----
        float ym1 = S1, ym2 = S2;
        xm1 = xm1_0; xm2 = xm2_0;
        #pragma unroll
        for (int k = 0; k < LCH; ++k) {
            float v  = xc[k];
            float f  = fmaf(B0, v, fmaf(B1, xm1, B2 * xm2));
            float yn = fmaf(nA1, ym1, fmaf(nA2, ym2, f));
            ym2 = ym1; ym1 = yn; xm2 = xm1; xm1 = v;
            xc[k] = yn;
        }
        __syncwarp();

        // ---- coalesced float4 store of this warp's slice ----
        float4* const yg4 = (float4*)(yg + t * TILE + w * WSLICE);
        const float4* const b4 = (const float4*)buf;
        #pragma unroll
        for (int i = lane; i < WSLICE / 4; i += 32)
            yg4[i] = b4[i];
    }
}

extern "C" void kernel_launch(void* const* d_in, const int* in_sizes, int n_in,
                              void* d_out, int out_size)
{
    const float* x  = (const float*)d_in[0];
    const float* b0 = (const float*)d_in[1];
    const float* b1 = (const float*)d_in[2];
    const float* b2 = (const float*)d_in[3];
    const float* a1 = (const float*)d_in[4];
    const float* a2 = (const float*)d_in[5];
    float* yo = (float*)d_out;

    biquad_kernel<<<NCH, NTHR>>>(x, b0, b1, b2, a1, a2, yo);
}